// round 15
// baseline (speedup 1.0000x reference)
#include <cuda_runtime.h>
#include <math.h>

#define NB 16
#define NC 256
#define NE 9216
#define NE4 (NE / 4)
#define KSEL 4096

// Scratch (no allocations allowed) — device globals, 16B-aligned via vector types.
__device__ float4 g_score4[NB * NE4];   // scores, viewed as float[NB*NE]
__device__ int4   g_pos4[NB * NE4];     // pos[e] = output slot if kept, -1 if dropped

// ---------------------------------------------------------------------------
// Kernel 1: score[b,e] = sum_c x[b,c,e]^2   (float4 over e, channel-split x8)
// grid = (NE4/32, NB) = (72, 16) = 1152 CTAs, block = 256.
// block = 32 e4-lanes x 8 channel-groups of 32 channels; SMEM reduce at end.
// Unroll 16: ~256B of loads in flight per thread (latency-limited regime).
// ---------------------------------------------------------------------------
__global__ __launch_bounds__(256) void score_kernel(const float4* __restrict__ x4) {
    __shared__ float4 part[8][32];
    const int tid = threadIdx.x;
    const int el  = tid & 31;          // e4 lane within block
    const int cg  = tid >> 5;          // channel group 0..7
    const int e4  = blockIdx.x * 32 + el;
    const int b   = blockIdx.y;

    const float4* p = x4 + ((size_t)b * NC + (size_t)cg * 32) * NE4 + e4;
    float ax = 0.f, ay = 0.f, az = 0.f, aw = 0.f;
#pragma unroll 16
    for (int c = 0; c < 32; ++c) {
        float4 v = __ldg(p + (size_t)c * NE4);
        ax = fmaf(v.x, v.x, ax);
        ay = fmaf(v.y, v.y, ay);
        az = fmaf(v.z, v.z, az);
        aw = fmaf(v.w, v.w, aw);
    }
    part[cg][el] = make_float4(ax, ay, az, aw);
    __syncthreads();
    if (tid < 32) {
        float4 s = part[0][tid];
#pragma unroll
        for (int g = 1; g < 8; ++g) {
            float4 q = part[g][tid];
            s.x += q.x; s.y += q.y; s.z += q.z; s.w += q.w;
        }
        g_score4[b * NE4 + blockIdx.x * 32 + tid] = s;
    }
}

// ---------------------------------------------------------------------------
// Block exclusive scan over 1024 threads (32 warps). wsum is shared[32].
// ---------------------------------------------------------------------------
__device__ __forceinline__ int block_exscan(int val, int t, int* wsum) {
    int lane = t & 31, w = t >> 5;
    int x = val;
#pragma unroll
    for (int d = 1; d < 32; d <<= 1) {
        int y = __shfl_up_sync(0xFFFFFFFFu, x, d);
        if (lane >= d) x += y;
    }
    __syncthreads();               // protect wsum reuse across calls
    if (lane == 31) wsum[w] = x;   // inclusive warp total
    __syncthreads();
    if (w == 0) {
        int s = wsum[lane];
        int xs = s;
#pragma unroll
        for (int d = 1; d < 32; d <<= 1) {
            int y = __shfl_up_sync(0xFFFFFFFFu, xs, d);
            if (lane >= d) xs += y;
        }
        wsum[lane] = xs - s;       // exclusive warp offsets
    }
    __syncthreads();
    return wsum[w] + x - val;      // exclusive for this thread
}

// Monotone float->uint order transform (valid scores >= 0 -> >= 0x80000000).
__device__ __forceinline__ unsigned int fkey(unsigned int bits) {
    return (bits & 0x80000000u) ? ~bits : (bits | 0x80000000u);
}

// ---------------------------------------------------------------------------
// Kernel 2: per-mesh K-th-largest threshold (MSD radix select, 4x8-bit) +
// stable tie-break by ascending index + forward position map.
// One CTA of 1024 threads per mesh (16 CTAs total). [champion version]
//  - uint4-vectorized key load, SMEM-resident keys
//  - 8-replica histogram (replica = warp&7), shuffle suffix scans
//  - pass-1 fast path (no ballot; all keys participate)
// ---------------------------------------------------------------------------
__global__ __launch_bounds__(1024) void select_kernel(const void* __restrict__ ec_raw) {
    __shared__ unsigned int skey[NE];        // 36 KB
    __shared__ unsigned int hist8[8][256];   // 8 KB, replicated histogram
    __shared__ unsigned int chunksum[8];
    __shared__ unsigned int choff[8];
    __shared__ unsigned int bcast[2];
    __shared__ int wsum[32];

    const int t = threadIdx.x;
    const int lane = t & 31, w = t >> 5;
    const int b = blockIdx.x;

    // edges_count dtype robustness: int64 vs int32 (jax x64 demotion).
    // Counts are always >= 8704, never 0, so ec32[1]==0 <=> int64 layout.
    const int* ec32 = (const int*)ec_raw;
    long long cnt;
    if (ec32[1] == 0) cnt = ((const long long*)ec_raw)[b];
    else              cnt = (long long)ec32[b];

    // Load order-transformed keys, vectorized (invalid edges -> key 0).
    {
        const uint4* sc4 = (const uint4*)(g_score4 + b * NE4);
#pragma unroll 3
        for (int q = t; q < NE4; q += 1024) {     // 2304 uint4 loads, 3 iters
            uint4 v = __ldg(sc4 + q);
            int e = q * 4;
            skey[e + 0] = (e + 0 < cnt) ? fkey(v.x) : 0u;
            skey[e + 1] = (e + 1 < cnt) ? fkey(v.y) : 0u;
            skey[e + 2] = (e + 2 < cnt) ? fkey(v.z) : 0u;
            skey[e + 3] = (e + 3 < cnt) ? fkey(v.w) : 0u;
        }
    }

    // 4-pass MSD radix select for the KSEL-th largest key.
    unsigned int prefix = 0, pmask = 0;
    int kth = KSEL;
    for (int shift = 24; shift >= 0; shift -= 8) {
        {   // clear 2048 histogram words (2 per thread)
            ((unsigned int*)hist8)[t] = 0;
            ((unsigned int*)hist8)[t + 1024] = 0;
        }
        __syncthreads();    // (also covers skey store on first pass)
        if (shift == 24) {
            // Pass 1 fast path: every key participates (pmask == 0).
#pragma unroll
            for (int e = t; e < NE; e += 1024) {
                unsigned int digit = skey[e] >> 24;
                unsigned int peers = __match_any_sync(0xFFFFFFFFu, digit);
                if (lane == __ffs(peers) - 1)
                    atomicAdd(&hist8[w & 7][digit], (unsigned int)__popc(peers));
            }
        } else {
#pragma unroll
            for (int e = t; e < NE; e += 1024) {   // exactly 9 uniform iterations
                unsigned int key = skey[e];
                bool ok = ((key & pmask) == prefix);
                unsigned int digit = (key >> shift) & 255u;
                unsigned int active = __ballot_sync(0xFFFFFFFFu, ok);
                if (ok) {
                    unsigned int peers = __match_any_sync(active, digit);
                    if (lane == __ffs(peers) - 1)
                        atomicAdd(&hist8[w & 7][digit], (unsigned int)__popc(peers));
                }
            }
        }
        __syncthreads();
        // Warps 0..7: bin v = w*32+lane. Merge replicas, warp suffix scan.
        unsigned int h = 0, s = 0;
        if (w < 8) {
            const int bin = w * 32 + lane;
#pragma unroll
            for (int r = 0; r < 8; ++r) h += hist8[r][bin];
            s = h;                                  // inclusive suffix in chunk
#pragma unroll
            for (int d = 1; d < 32; d <<= 1) {
                unsigned int y = __shfl_down_sync(0xFFFFFFFFu, s, d);
                if (lane + d < 32) s += y;
            }
            if (lane == 0) chunksum[w] = s;         // chunk total
        }
        __syncthreads();
        if (t < 8) {                                 // exclusive suffix of chunks
            unsigned int cs = chunksum[t], sf = cs;
#pragma unroll
            for (int d = 1; d < 8; d <<= 1) {
                unsigned int y = __shfl_down_sync(0xFFu, sf, d);
                if (t + d < 8) sf += y;
            }
            choff[t] = sf - cs;
        }
        __syncthreads();
        if (w < 8) {
            unsigned int Sv = s + choff[w];          // suffix count from bin v
            unsigned int Sn = Sv - h;                // suffix count from v+1
            if ((int)Sv >= kth && (int)Sn < kth) {   // exactly one bin matches
                bcast[0] = (unsigned int)(w * 32 + lane);
                bcast[1] = (unsigned int)(kth - (int)Sn);
            }
        }
        __syncthreads();
        prefix |= bcast[0] << shift;
        pmask  |= 0xFFu << shift;
        kth = (int)bcast[1];
        __syncthreads();
    }

    const unsigned int T = prefix;   // key of the KSEL-th largest element
    const int needed_eq = kth;       // # of ==T elements to keep (lowest idx first)

    // Per-thread contiguous chunk of 9 elements (1024 * 9 = 9216).
    const int base = t * 9;
    unsigned int keys[9];
#pragma unroll
    for (int i = 0; i < 9; ++i) keys[i] = skey[base + i];

    // Pass A: rank among ==T elements (index order).
    int eqpre[9]; int eqcnt = 0;
#pragma unroll
    for (int i = 0; i < 9; ++i) { eqpre[i] = eqcnt; eqcnt += (keys[i] == T); }
    int eqoff = block_exscan(eqcnt, t, wsum);

    // Pass B: keep-flag compaction -> forward position map.
    int kpre[9]; int kcnt = 0;
#pragma unroll
    for (int i = 0; i < 9; ++i) {
        bool keep = (keys[i] > T) || (keys[i] == T && (eqoff + eqpre[i]) < needed_eq);
        kpre[i] = kcnt; kcnt += keep;
    }
    int koff = block_exscan(kcnt, t, wsum);
    int* pos = (int*)g_pos4;
#pragma unroll
    for (int i = 0; i < 9; ++i) {
        bool keep = (keys[i] > T) || (keys[i] == T && (eqoff + eqpre[i]) < needed_eq);
        pos[b * NE + base + i] = keep ? (koff + kpre[i]) : -1;
    }
}

// ---------------------------------------------------------------------------
// Kernel 3: forward scatter — fully coalesced float4 reads of x; kept
// elements written to their dense ascending output slots (L2 merges the
// predicated STG.32s into full dirty sectors). Threads whose 4 edges are all
// dropped (~9.5%) exit before issuing their 8 loads (sign-bit AND test).
// grid = (NE4/256, NC/8, NB), block = 256. pos reused across 8 channels.
// ---------------------------------------------------------------------------
__global__ void scatter_kernel(const float4* __restrict__ x4,
                               float* __restrict__ out) {
    int e4 = blockIdx.x * blockDim.x + threadIdx.x;  // 0..NE4-1
    int c0 = blockIdx.y * 8;
    int b  = blockIdx.z;

    int4 pos = g_pos4[b * NE4 + e4];
    if ((pos.x & pos.y & pos.z & pos.w) < 0)
        return;                                      // all 4 edges dropped

    const float4* xp = x4 + ((size_t)b * NC + c0) * NE4 + e4;
    float* op = out + ((size_t)b * NC + c0) * KSEL;

#pragma unroll
    for (int j = 0; j < 8; ++j) {
        float4 v = __ldg(xp + (size_t)j * NE4);
        float* o = op + (size_t)j * KSEL;
        if (pos.x >= 0) o[pos.x] = v.x;
        if (pos.y >= 0) o[pos.y] = v.y;
        if (pos.z >= 0) o[pos.z] = v.z;
        if (pos.w >= 0) o[pos.w] = v.w;
    }
}

// ---------------------------------------------------------------------------
extern "C" void kernel_launch(void* const* d_in, const int* in_sizes, int n_in,
                              void* d_out, int out_size) {
    const float4* x4 = (const float4*)d_in[0];
    const void* ec = d_in[1];     // edges_count (int64 or int32; detected on device)
    float* out = (float*)d_out;

    score_kernel<<<dim3(NE4 / 32, NB), 256>>>(x4);
    select_kernel<<<NB, 1024>>>(ec);
    scatter_kernel<<<dim3(NE4 / 256, NC / 8, NB), 256>>>(x4, out);
}

// round 16
// speedup vs baseline: 1.0029x; 1.0029x over previous
#include <cuda_runtime.h>
#include <math.h>

#define NB 16
#define NC 256
#define NE 9216
#define NE4 (NE / 4)
#define KSEL 4096

// Scratch (no allocations allowed) — device globals, 16B-aligned via vector types.
__device__ float4 g_score4[NB * NE4];   // scores, viewed as float[NB*NE]
__device__ int4   g_pos4[NB * NE4];     // pos[e] = output slot if kept, -1 if dropped

// ---------------------------------------------------------------------------
// Kernel 1: score[b,e] = sum_c x[b,c,e]^2   (float4 over e, channel-split x8)
// grid = (NE4/32, NB) = (72, 16) = 1152 CTAs, block = 256.
// block = 32 e4-lanes x 8 channel-groups of 32 channels; SMEM reduce at end.
// ---------------------------------------------------------------------------
__global__ __launch_bounds__(256) void score_kernel(const float4* __restrict__ x4) {
    __shared__ float4 part[8][32];
    const int tid = threadIdx.x;
    const int el  = tid & 31;          // e4 lane within block
    const int cg  = tid >> 5;          // channel group 0..7
    const int e4  = blockIdx.x * 32 + el;
    const int b   = blockIdx.y;

    const float4* p = x4 + ((size_t)b * NC + (size_t)cg * 32) * NE4 + e4;
    float ax = 0.f, ay = 0.f, az = 0.f, aw = 0.f;
#pragma unroll 8
    for (int c = 0; c < 32; ++c) {
        float4 v = __ldg(p + (size_t)c * NE4);
        ax = fmaf(v.x, v.x, ax);
        ay = fmaf(v.y, v.y, ay);
        az = fmaf(v.z, v.z, az);
        aw = fmaf(v.w, v.w, aw);
    }
    part[cg][el] = make_float4(ax, ay, az, aw);
    __syncthreads();
    if (tid < 32) {
        float4 s = part[0][tid];
#pragma unroll
        for (int g = 1; g < 8; ++g) {
            float4 q = part[g][tid];
            s.x += q.x; s.y += q.y; s.z += q.z; s.w += q.w;
        }
        g_score4[b * NE4 + blockIdx.x * 32 + tid] = s;
    }
}

// ---------------------------------------------------------------------------
// Block exclusive scan over 1024 threads (32 warps). wsum is shared[32].
// ---------------------------------------------------------------------------
__device__ __forceinline__ int block_exscan(int val, int t, int* wsum) {
    int lane = t & 31, w = t >> 5;
    int x = val;
#pragma unroll
    for (int d = 1; d < 32; d <<= 1) {
        int y = __shfl_up_sync(0xFFFFFFFFu, x, d);
        if (lane >= d) x += y;
    }
    __syncthreads();               // protect wsum reuse across calls
    if (lane == 31) wsum[w] = x;   // inclusive warp total
    __syncthreads();
    if (w == 0) {
        int s = wsum[lane];
        int xs = s;
#pragma unroll
        for (int d = 1; d < 32; d <<= 1) {
            int y = __shfl_up_sync(0xFFFFFFFFu, xs, d);
            if (lane >= d) xs += y;
        }
        wsum[lane] = xs - s;       // exclusive warp offsets
    }
    __syncthreads();
    return wsum[w] + x - val;      // exclusive for this thread
}

// Monotone float->uint order transform (valid scores >= 0 -> >= 0x80000000).
__device__ __forceinline__ unsigned int fkey(unsigned int bits) {
    return (bits & 0x80000000u) ? ~bits : (bits | 0x80000000u);
}

// ---------------------------------------------------------------------------
// Kernel 2: per-mesh K-th-largest threshold (MSD radix select, 4x8-bit) +
// stable tie-break by ascending index + forward position map.
// One CTA of 1024 threads per mesh (16 CTAs total). [champion version]
//  - uint4-vectorized key load, SMEM-resident keys
//  - 8-replica histogram (replica = warp&7), shuffle suffix scans
//  - pass-1 fast path (no ballot; all keys participate)
// ---------------------------------------------------------------------------
__global__ __launch_bounds__(1024) void select_kernel(const void* __restrict__ ec_raw) {
    __shared__ unsigned int skey[NE];        // 36 KB
    __shared__ unsigned int hist8[8][256];   // 8 KB, replicated histogram
    __shared__ unsigned int chunksum[8];
    __shared__ unsigned int choff[8];
    __shared__ unsigned int bcast[2];
    __shared__ int wsum[32];

    const int t = threadIdx.x;
    const int lane = t & 31, w = t >> 5;
    const int b = blockIdx.x;

    // edges_count dtype robustness: int64 vs int32 (jax x64 demotion).
    // Counts are always >= 8704, never 0, so ec32[1]==0 <=> int64 layout.
    const int* ec32 = (const int*)ec_raw;
    long long cnt;
    if (ec32[1] == 0) cnt = ((const long long*)ec_raw)[b];
    else              cnt = (long long)ec32[b];

    // Load order-transformed keys, vectorized (invalid edges -> key 0).
    {
        const uint4* sc4 = (const uint4*)(g_score4 + b * NE4);
#pragma unroll 3
        for (int q = t; q < NE4; q += 1024) {     // 2304 uint4 loads, 3 iters
            uint4 v = __ldg(sc4 + q);
            int e = q * 4;
            skey[e + 0] = (e + 0 < cnt) ? fkey(v.x) : 0u;
            skey[e + 1] = (e + 1 < cnt) ? fkey(v.y) : 0u;
            skey[e + 2] = (e + 2 < cnt) ? fkey(v.z) : 0u;
            skey[e + 3] = (e + 3 < cnt) ? fkey(v.w) : 0u;
        }
    }

    // 4-pass MSD radix select for the KSEL-th largest key.
    unsigned int prefix = 0, pmask = 0;
    int kth = KSEL;
    for (int shift = 24; shift >= 0; shift -= 8) {
        {   // clear 2048 histogram words (2 per thread)
            ((unsigned int*)hist8)[t] = 0;
            ((unsigned int*)hist8)[t + 1024] = 0;
        }
        __syncthreads();    // (also covers skey store on first pass)
        if (shift == 24) {
            // Pass 1 fast path: every key participates (pmask == 0).
#pragma unroll
            for (int e = t; e < NE; e += 1024) {
                unsigned int digit = skey[e] >> 24;
                unsigned int peers = __match_any_sync(0xFFFFFFFFu, digit);
                if (lane == __ffs(peers) - 1)
                    atomicAdd(&hist8[w & 7][digit], (unsigned int)__popc(peers));
            }
        } else {
#pragma unroll
            for (int e = t; e < NE; e += 1024) {   // exactly 9 uniform iterations
                unsigned int key = skey[e];
                bool ok = ((key & pmask) == prefix);
                unsigned int digit = (key >> shift) & 255u;
                unsigned int active = __ballot_sync(0xFFFFFFFFu, ok);
                if (ok) {
                    unsigned int peers = __match_any_sync(active, digit);
                    if (lane == __ffs(peers) - 1)
                        atomicAdd(&hist8[w & 7][digit], (unsigned int)__popc(peers));
                }
            }
        }
        __syncthreads();
        // Warps 0..7: bin v = w*32+lane. Merge replicas, warp suffix scan.
        unsigned int h = 0, s = 0;
        if (w < 8) {
            const int bin = w * 32 + lane;
#pragma unroll
            for (int r = 0; r < 8; ++r) h += hist8[r][bin];
            s = h;                                  // inclusive suffix in chunk
#pragma unroll
            for (int d = 1; d < 32; d <<= 1) {
                unsigned int y = __shfl_down_sync(0xFFFFFFFFu, s, d);
                if (lane + d < 32) s += y;
            }
            if (lane == 0) chunksum[w] = s;         // chunk total
        }
        __syncthreads();
        if (t < 8) {                                 // exclusive suffix of chunks
            unsigned int cs = chunksum[t], sf = cs;
#pragma unroll
            for (int d = 1; d < 8; d <<= 1) {
                unsigned int y = __shfl_down_sync(0xFFu, sf, d);
                if (t + d < 8) sf += y;
            }
            choff[t] = sf - cs;
        }
        __syncthreads();
        if (w < 8) {
            unsigned int Sv = s + choff[w];          // suffix count from bin v
            unsigned int Sn = Sv - h;                // suffix count from v+1
            if ((int)Sv >= kth && (int)Sn < kth) {   // exactly one bin matches
                bcast[0] = (unsigned int)(w * 32 + lane);
                bcast[1] = (unsigned int)(kth - (int)Sn);
            }
        }
        __syncthreads();
        prefix |= bcast[0] << shift;
        pmask  |= 0xFFu << shift;
        kth = (int)bcast[1];
        __syncthreads();
    }

    const unsigned int T = prefix;   // key of the KSEL-th largest element
    const int needed_eq = kth;       // # of ==T elements to keep (lowest idx first)

    // Per-thread contiguous chunk of 9 elements (1024 * 9 = 9216).
    const int base = t * 9;
    unsigned int keys[9];
#pragma unroll
    for (int i = 0; i < 9; ++i) keys[i] = skey[base + i];

    // Pass A: rank among ==T elements (index order).
    int eqpre[9]; int eqcnt = 0;
#pragma unroll
    for (int i = 0; i < 9; ++i) { eqpre[i] = eqcnt; eqcnt += (keys[i] == T); }
    int eqoff = block_exscan(eqcnt, t, wsum);

    // Pass B: keep-flag compaction -> forward position map.
    int kpre[9]; int kcnt = 0;
#pragma unroll
    for (int i = 0; i < 9; ++i) {
        bool keep = (keys[i] > T) || (keys[i] == T && (eqoff + eqpre[i]) < needed_eq);
        kpre[i] = kcnt; kcnt += keep;
    }
    int koff = block_exscan(kcnt, t, wsum);
    int* pos = (int*)g_pos4;
#pragma unroll
    for (int i = 0; i < 9; ++i) {
        bool keep = (keys[i] > T) || (keys[i] == T && (eqoff + eqpre[i]) < needed_eq);
        pos[b * NE + base + i] = keep ? (koff + kpre[i]) : -1;
    }
}

// ---------------------------------------------------------------------------
// Kernel 3: forward scatter — fully coalesced float4 reads of x; kept
// elements written to their dense ascending output slots (L2 merges the
// predicated STG.32s into full dirty sectors). Threads whose 4 edges are all
// dropped (~9.5%) exit before issuing their 8 loads (sign-bit AND test).
// grid = (NE4/256, NC/8, NB), block = 256. pos reused across 8 channels.
// ---------------------------------------------------------------------------
__global__ void scatter_kernel(const float4* __restrict__ x4,
                               float* __restrict__ out) {
    int e4 = blockIdx.x * blockDim.x + threadIdx.x;  // 0..NE4-1
    int c0 = blockIdx.y * 8;
    int b  = blockIdx.z;

    int4 pos = g_pos4[b * NE4 + e4];
    if ((pos.x & pos.y & pos.z & pos.w) < 0)
        return;                                      // all 4 edges dropped

    const float4* xp = x4 + ((size_t)b * NC + c0) * NE4 + e4;
    float* op = out + ((size_t)b * NC + c0) * KSEL;

#pragma unroll
    for (int j = 0; j < 8; ++j) {
        float4 v = __ldg(xp + (size_t)j * NE4);
        float* o = op + (size_t)j * KSEL;
        if (pos.x >= 0) o[pos.x] = v.x;
        if (pos.y >= 0) o[pos.y] = v.y;
        if (pos.z >= 0) o[pos.z] = v.z;
        if (pos.w >= 0) o[pos.w] = v.w;
    }
}

// ---------------------------------------------------------------------------
extern "C" void kernel_launch(void* const* d_in, const int* in_sizes, int n_in,
                              void* d_out, int out_size) {
    const float4* x4 = (const float4*)d_in[0];
    const void* ec = d_in[1];     // edges_count (int64 or int32; detected on device)
    float* out = (float*)d_out;

    score_kernel<<<dim3(NE4 / 32, NB), 256>>>(x4);
    select_kernel<<<NB, 1024>>>(ec);
    scatter_kernel<<<dim3(NE4 / 256, NC / 8, NB), 256>>>(x4, out);
}